// round 5
// baseline (speedup 1.0000x reference)
#include <cuda_runtime.h>
#include <cstdint>

#define SH 68                    // smem row stride in floats
#define SZ (64 * SH)             // padded 64x64 matrix (floats)
#define NHEADS 8
#define NMAX 2048
#define MASK56 0x00FFFFFFFFFFFFFFull

// ---------------- device scratch ----------------
__device__ float g_powers[NHEADS][16][4096];     // g_powers[h][k] = B_h^k
__device__ float g_sos[4096];
__device__ int   g_key[NMAX];
__device__ unsigned long long g_pack[NMAX];      // len<<56 | 2-bit codes
__device__ int   g_perm[NMAX];
__device__ unsigned g_done_prep;                 // 81 producers (80 powers + sos)
__device__ unsigned g_grp;

// packed f32x2 FFMA: acc(pair) += (a,a) * bp(pair)
#define FFMA2(acc, a, bp)                                                     \
    asm("{\n\t.reg .b64 t;\n\tmov.b64 t, {%1,%1};\n\t"                        \
        "fma.rn.f32x2 %0, t, %2, %0;\n\t}"                                    \
        : "+l"(acc) : "f"(a), "l"(bp))

#define BULK_S2G(gdst, ssrc, bytes)                                           \
    asm volatile("cp.async.bulk.global.shared::cta.bulk_group [%0], [%1], %2;"\
                 :: "l"(gdst), "r"(ssrc), "r"(bytes) : "memory")
#define BULK_COMMIT() asm volatile("cp.async.bulk.commit_group;" ::: "memory")
#define BULK_WAIT0()  asm volatile("cp.async.bulk.wait_group 0;" ::: "memory")
#define FENCE_ASYNC() asm volatile("fence.proxy.async;" ::: "memory")

__device__ __forceinline__ float f2lo(unsigned long long v) {
    return __uint_as_float((unsigned)(v & 0xffffffffull));
}
__device__ __forceinline__ float f2hi(unsigned long long v) {
    return __uint_as_float((unsigned)(v >> 32));
}
__device__ __forceinline__ uint32_t smem_u32(const void* p) {
    return (uint32_t)__cvta_generic_to_shared(p);
}

// ---- 64x64 mm core (512 thr): acc[i] = sum_j AT[j][r0+i] * B[j][c0..c0+1]
__device__ __forceinline__ void mm_acc(const float* __restrict__ AT,
                                       const float* __restrict__ B,
                                       unsigned long long acc[4],
                                       int r0, int c0) {
    const float* ap = AT + r0;
    const float* bp = B + c0;
    acc[0] = acc[1] = acc[2] = acc[3] = 0ull;
#pragma unroll 8
    for (int j = 0; j < 64; j++) {
        float4 x = *(const float4*)(ap + j * SH);
        unsigned long long b2 = *(const unsigned long long*)(bp + j * SH);
        FFMA2(acc[0], x.x, b2); FFMA2(acc[1], x.y, b2);
        FFMA2(acc[2], x.z, b2); FFMA2(acc[3], x.w, b2);
    }
}

__global__ void reset_kernel() {
    if (threadIdx.x == 0) { g_done_prep = 0u; g_grp = 0u; }
}

// =================== fused kernel ===================
// b 0..79  : prepare (h = b/10, k = b%10 + 1)
// b 80     : sos expm
// b 81     : grouping
// b 82..2129   : steps rows (need g_grp)
// b 2130..4177 : maps tiles via TMA bulk (need g_grp + g_done_prep==81)
__global__ void __launch_bounds__(512, 2)
fused_kernel(const float* __restrict__ raw, const int* __restrict__ pw,
             int L, float* __restrict__ out, int has_steps) {
    extern __shared__ float sm[];
    int b = blockIdx.x;
    int tid = threadIdx.x;

    // ---------------- producers ----------------
    if (b < 81) {
        int h, kk;
        const float* A;
        if (b == 80) { h = -1; kk = 1; A = raw + (size_t)16 * 4096; }
        else         { h = b / 10; kk = b % 10 + 1; A = raw + (size_t)(8 + h) * 4096; }

        float* M  = sm + 0 * SZ;
        float* MT = sm + 1 * SZ;     // dead after mm2; reused as W2
        float* P2 = sm + 2 * SZ;
        float* P4 = sm + 3 * SZ;
        float* W1 = sm + 4 * SZ;
        float* W2 = MT;

        int w = tid >> 5, l = tid & 31;
        int r0 = (w >> 2) * 16 + (l >> 3) * 4;
        int c0 = (w & 3) * 16 + (l & 7) * 2;

        float scale = (float)kk * (1.0f / 64.0f);
        for (int i = tid; i < 4096; i += 512) {
            int rr = i >> 6, cc = i & 63;
            float v = (A[rr * 64 + cc] - A[cc * 64 + rr]) * scale;
            M[rr * SH + cc]  = v;
            MT[cc * SH + rr] = v;
        }
        __syncthreads();

        unsigned long long acc[4], p3[4];

        mm_acc(MT, M, acc, r0, c0);                // P2 = M^2 (symmetric)
#pragma unroll
        for (int i = 0; i < 4; i++)
            *(unsigned long long*)(P2 + (r0 + i) * SH + c0) = acc[i];
        __syncthreads();

        mm_acc(MT, P2, p3, r0, c0);                // P3 kept in registers
        mm_acc(P2, P2, acc, r0, c0);               // P4 = M^4 (symmetric)
#pragma unroll
        for (int i = 0; i < 4; i++) {
            int r = r0 + i;
            *(unsigned long long*)(P4 + r * SH + c0) = acc[i];
            float2 mv  = *(const float2*)(M  + r * SH + c0);
            float2 p2v = *(const float2*)(P2 + r * SH + c0);
            float d0 = (r == c0)     ? 1.f : 0.f;
            float d1 = (r == c0 + 1) ? 1.f : 0.f;
            float2 wv;
            wv.x = 2.48015873e-5f * d0 + 2.75573192e-6f * mv.x
                 + 2.75573192e-7f * p2v.x + 2.50521084e-8f * f2lo(p3[i])
                 + 2.08767570e-9f * f2lo(acc[i]);
            wv.y = 2.48015873e-5f * d1 + 2.75573192e-6f * mv.y
                 + 2.75573192e-7f * p2v.y + 2.50521084e-8f * f2hi(p3[i])
                 + 2.08767570e-9f * f2hi(acc[i]);
            *(float2*)(W1 + r * SH + c0) = wv;
        }
        __syncthreads();

        mm_acc(P4, W1, acc, r0, c0);               // W2 = P4*B2' + B1
#pragma unroll
        for (int i = 0; i < 4; i++) {
            int r = r0 + i;
            float2 mv  = *(const float2*)(M  + r * SH + c0);
            float2 p2v = *(const float2*)(P2 + r * SH + c0);
            float d0 = (r == c0)     ? 1.f : 0.f;
            float d1 = (r == c0 + 1) ? 1.f : 0.f;
            float2 wv;
            wv.x = f2lo(acc[i]) + (1.f / 24.f) * d0 + (1.f / 120.f) * mv.x
                 + 1.38888889e-3f * p2v.x + 1.98412698e-4f * f2lo(p3[i]);
            wv.y = f2hi(acc[i]) + (1.f / 24.f) * d1 + (1.f / 120.f) * mv.y
                 + 1.38888889e-3f * p2v.y + 1.98412698e-4f * f2hi(p3[i]);
            *(float2*)(W2 + r * SH + c0) = wv;
        }
        __syncthreads();

        mm_acc(P4, W2, acc, r0, c0);               // E = P4*W2 + B0
        float* dst = (h < 0) ? g_sos : g_powers[h][kk];
#pragma unroll
        for (int i = 0; i < 4; i++) {
            int r = r0 + i;
            float2 mv  = *(const float2*)(M  + r * SH + c0);
            float2 p2v = *(const float2*)(P2 + r * SH + c0);
            float d0 = (r == c0)     ? 1.f : 0.f;
            float d1 = (r == c0 + 1) ? 1.f : 0.f;
            float ex = f2lo(acc[i]) + d0 + mv.x + 0.5f * p2v.x + (1.f / 6.f) * f2lo(p3[i]);
            float ey = f2hi(acc[i]) + d1 + mv.y + 0.5f * p2v.y + (1.f / 6.f) * f2hi(p3[i]);
            *(float2*)(dst + r * 64 + c0) = make_float2(ex, ey);
            if (h >= 0 && kk == 1)
                *(float2*)(g_powers[h][0] + r * 64 + c0) = make_float2(d0, d1);
        }
        __threadfence();
        __syncthreads();
        if (tid == 0) atomicAdd(&g_done_prep, 1u);
        return;
    }

    if (b == 81) {   // ---------------- grouping ----------------
        int* cnt = (int*)sm;
        int* off = cnt + 32;
        if (tid < 20) cnt[tid] = 0;
        __syncthreads();
        for (int n = tid; n < NMAX; n += 512) {
            const int* p = pw + (size_t)n * L;
            int c = 0, len = 0;
            unsigned long long pack = 0ull;
            for (int t = 0; t < L; t++) {
                int wv = p[t];
                int code = (wv == -1) ? 0 : wv;
                pack |= ((unsigned long long)(code & 3)) << (2 * t);
                if (wv != 3) len++;          // PAD = 3
                if (wv == 1) c++;            // only step==1 hits the gate
            }
            int key = (p[0] == -1) ? 100 : c;
            g_key[n] = key;
            g_pack[n] = pack | ((unsigned long long)len << 56);
            atomicAdd(&cnt[(key == 100) ? 16 : key], 1);
        }
        __syncthreads();
        if (tid == 0) { int s = 0; for (int q = 0; q < 20; q++) { off[q] = s; s += cnt[q]; } }
        __syncthreads();
        for (int n = tid; n < NMAX; n += 512) {
            int key = g_key[n];
            int pos = atomicAdd(&off[(key == 100) ? 16 : key], 1);
            g_perm[pos] = n;
        }
        __threadfence();
        __syncthreads();
        if (tid == 0) atomicAdd(&g_grp, 1u);
        return;
    }

    if (b < 2130) {  // ---------------- steps rows ----------------
        if (!has_steps) return;
        if (tid == 0) { while (atomicAdd(&g_grp, 0u) < 1u) __nanosleep(128); }
        __syncthreads();
        __threadfence();
        int i = b - 82;
        unsigned long long pi = __ldcg(&g_pack[i]);
        int li = (int)(pi >> 56);
        int j0 = tid << 2;
        float v[4];
#pragma unroll
        for (int q = 0; q < 4; q++) {
            unsigned long long pj = __ldcg(&g_pack[j0 + q]);
            int lj = (int)(pj >> 56);
            unsigned long long d = (pi ^ pj) & MASK56;
            int pos = d ? ((__ffsll((long long)d) - 1) >> 1) : 64;
            int mn = min(li, lj), mx = max(li, lj);
            v[q] = (float)(mx - min(pos, mn));
        }
        float* steps_out = out + (size_t)NMAX * NHEADS * 4096;
        __stcs((float4*)(steps_out + (size_t)i * NMAX + j0),
               make_float4(v[0], v[1], v[2], v[3]));
        return;
    }

    // ---------------- maps tiles: smem stage + TMA bulk stores ----------
    {
        if (tid == 0) {
            while (atomicAdd(&g_grp, 0u) < 1u) __nanosleep(128);
            while (atomicAdd(&g_done_prep, 0u) < 81u) __nanosleep(256);
        }
        __syncthreads();
        __threadfence();
        int b2 = b - 2130;
        int h = b2 & 7;
        int base = (b2 >> 3) << 3;
        uint32_t s_addr = smem_u32(sm);
        int cached = -12345;
#pragma unroll 1
        for (int e = 0; e < 8; e++) {
            int n = __ldcg(&g_perm[base + e]);
            int key = __ldcg(&g_key[n]);
            if (key != cached) {
                if (tid == 0) BULK_WAIT0();      // drain reads before overwrite
                __syncthreads();
                const float4* src = (key == 100) ? (const float4*)g_sos
                                                 : (const float4*)g_powers[h][key];
                float4* dst4 = (float4*)sm;
                dst4[tid]       = __ldcg(src + tid);
                dst4[tid + 512] = __ldcg(src + tid + 512);
                __syncthreads();
                if (tid == 0) FENCE_ASYNC();
                cached = key;
            }
            if (tid == 0) {
                const float* gdst = out + ((size_t)((unsigned)(n * NHEADS + h)) << 12);
                BULK_S2G(gdst, s_addr, 16384);
                BULK_COMMIT();
            }
        }
        if (tid == 0) BULK_WAIT0();
        __syncthreads();
    }
}

// ---------------- launch --------------------------------------------------
extern "C" void kernel_launch(void* const* d_in, const int* in_sizes, int n_in,
                              void* d_out, int out_size) {
    const float* raw = (const float*)d_in[0];
    const int*   pw  = (const int*)d_in[1];
    const int L = in_sizes[1] / NMAX;
    float* out = (float*)d_out;

    size_t maps_elems = (size_t)NMAX * NHEADS * 4096;
    int has_steps = ((size_t)out_size >= maps_elems + (size_t)NMAX * NMAX) ? 1 : 0;

    size_t smem = 5ull * SZ * sizeof(float);   // 87040 B -> 2 blocks/SM
    cudaFuncSetAttribute(fused_kernel, cudaFuncAttributeMaxDynamicSharedMemorySize,
                         (int)smem);

    reset_kernel<<<1, 32>>>();
    fused_kernel<<<82 + 2048 + 2048, 512, smem>>>(raw, pw, L, out, has_steps);
}

// round 6
// speedup vs baseline: 1.3090x; 1.3090x over previous
#include <cuda_runtime.h>
#include <cstdint>

#define SH 68                    // smem row stride in floats
#define SZ (64 * SH)             // padded 64x64 matrix (floats)
#define NHEADS 8
#define NMAX 2048
#define MASK56 0x00FFFFFFFFFFFFFFull

// ---------------- device scratch ----------------
__device__ float g_powers[NHEADS][16][4096];     // g_powers[h][k] = B_h^k
__device__ float g_sos[4096];
__device__ int   g_key[NMAX];
__device__ int   g_perm[NMAX];

// packed f32x2 FFMA: acc(pair) += (a,a) * bp(pair)
#define FFMA2(acc, a, bp)                                                     \
    asm("{\n\t.reg .b64 t;\n\tmov.b64 t, {%1,%1};\n\t"                        \
        "fma.rn.f32x2 %0, t, %2, %0;\n\t}"                                    \
        : "+l"(acc) : "f"(a), "l"(bp))

__device__ __forceinline__ float f2lo(unsigned long long v) {
    return __uint_as_float((unsigned)(v & 0xffffffffull));
}
__device__ __forceinline__ float f2hi(unsigned long long v) {
    return __uint_as_float((unsigned)(v >> 32));
}

// ---- 64x64 mm core (512 thr): acc[i] = sum_j AT[j][r0+i] * B[j][c0..c0+1]
// i.e. result = ATt * B. For skew inputs we pass M (=-Mt) or P3 (=-P3t)
// directly and negate in the epilogue.
__device__ __forceinline__ void mm_acc(const float* __restrict__ AT,
                                       const float* __restrict__ B,
                                       unsigned long long acc[4],
                                       int r0, int c0) {
    const float* ap = AT + r0;
    const float* bp = B + c0;
    acc[0] = acc[1] = acc[2] = acc[3] = 0ull;
#pragma unroll 8
    for (int j = 0; j < 64; j++) {
        float4 x = *(const float4*)(ap + j * SH);
        unsigned long long b2 = *(const unsigned long long*)(bp + j * SH);
        FFMA2(acc[0], x.x, b2); FFMA2(acc[1], x.y, b2);
        FFMA2(acc[2], x.z, b2); FFMA2(acc[3], x.w, b2);
    }
}

// =================== kernel A: prepare + grouping + steps ===================
// b 0..79  : expm(k*H_h)  (h = b/10, k = b%10 + 1)     [deg-9 PS, 4 matmuls]
// b 80     : expm(H_sos)
// b 81     : grouping (key + perm for maps)
// b 82..337: steps, 8 rows per block (self-contained, reads pw directly)
__global__ void __launch_bounds__(512, 2)
kernelA(const float* __restrict__ raw, const int* __restrict__ pw,
        int L, float* __restrict__ steps_out, int has_steps) {
    extern __shared__ float sm[];
    int b = blockIdx.x;
    int tid = threadIdx.x;

    if (b >= 82) {   // ---------------- steps ----------------
        if (!has_steps) return;
        unsigned long long* tbl = (unsigned long long*)sm;   // 2048 packs, 16 KB
#pragma unroll
        for (int q = 0; q < 4; q++) {
            int n = (tid << 2) + q;
            const int* p = pw + (size_t)n * L;
            unsigned long long pack = 0ull;
            int len = 0;
            for (int t = 0; t < L; t++) {
                int wv = p[t];
                int code = (wv == -1) ? 0 : wv;
                pack |= ((unsigned long long)(code & 3)) << (2 * t);
                if (wv != 3) len++;                  // PAD = 3
            }
            tbl[n] = pack | ((unsigned long long)len << 56);
        }
        __syncthreads();
        int i0 = (b - 82) << 3;
        int j0 = tid << 2;
        unsigned long long pj0 = tbl[j0], pj1 = tbl[j0 + 1];
        unsigned long long pj2 = tbl[j0 + 2], pj3 = tbl[j0 + 3];
#pragma unroll
        for (int rr = 0; rr < 8; rr++) {
            int i = i0 + rr;
            unsigned long long pi = tbl[i];
            int li = (int)(pi >> 56);
            float v[4];
            unsigned long long pjs[4] = {pj0, pj1, pj2, pj3};
#pragma unroll
            for (int q = 0; q < 4; q++) {
                unsigned long long pj = pjs[q];
                int lj = (int)(pj >> 56);
                unsigned long long d = (pi ^ pj) & MASK56;
                int pos = d ? ((__ffsll((long long)d) - 1) >> 1) : 64;
                int mn = min(li, lj), mx = max(li, lj);
                v[q] = (float)(mx - min(pos, mn));
            }
            __stcs((float4*)(steps_out + (size_t)i * NMAX + j0),
                   make_float4(v[0], v[1], v[2], v[3]));
        }
        return;
    }

    if (b == 81) {   // ---------------- grouping ----------------
        int* cnt = (int*)sm;
        int* off = cnt + 32;
        if (tid < 20) cnt[tid] = 0;
        __syncthreads();
        for (int n = tid; n < NMAX; n += 512) {
            const int* p = pw + (size_t)n * L;
            int c = 0;
            for (int t = 0; t < L; t++) c += (p[t] == 1);
            int key = (p[0] == -1) ? 100 : c;
            g_key[n] = key;
            atomicAdd(&cnt[(key == 100) ? 16 : key], 1);
        }
        __syncthreads();
        if (tid == 0) { int s = 0; for (int q = 0; q < 20; q++) { off[q] = s; s += cnt[q]; } }
        __syncthreads();
        for (int n = tid; n < NMAX; n += 512) {
            int key = g_key[n];
            int pos = atomicAdd(&off[(key == 100) ? 16 : key], 1);
            g_perm[pos] = n;
        }
        return;
    }

    // ---------------- prepare: B_h^k = expm(k*H_h), deg-9 PS --------------
    int h, kk;
    const float* A;
    if (b == 80) { h = -1; kk = 1; A = raw + (size_t)16 * 4096; }
    else         { h = b / 10; kk = b % 10 + 1; A = raw + (size_t)(8 + h) * 4096; }

    float* M  = sm + 0 * SZ;
    float* P2 = sm + 1 * SZ;
    float* P3 = sm + 2 * SZ;
    float* W  = sm + 3 * SZ;

    int w = tid >> 5, l = tid & 31;
    int r0 = (w >> 2) * 16 + (l >> 3) * 4;
    int c0 = (w & 3) * 16 + (l & 7) * 2;

    float scale = (float)kk * (1.0f / 64.0f);
    for (int i = tid; i < 4096; i += 512) {
        int rr = i >> 6, cc = i & 63;
        M[rr * SH + cc] = (A[rr * 64 + cc] - A[cc * 64 + rr]) * scale;
    }
    __syncthreads();

    unsigned long long acc[4];

    // P2 = M*M = -(Mt*M)
    mm_acc(M, M, acc, r0, c0);
#pragma unroll
    for (int i = 0; i < 4; i++) {
        float2 p = make_float2(-f2lo(acc[i]), -f2hi(acc[i]));
        *(float2*)(P2 + (r0 + i) * SH + c0) = p;
    }
    __syncthreads();

    // P3 = M*P2 = -(Mt*P2); fused: W = B2' = I/720 + M/5040 + P2/40320 + P3/362880
    mm_acc(M, P2, acc, r0, c0);
#pragma unroll
    for (int i = 0; i < 4; i++) {
        int r = r0 + i;
        float p3x = -f2lo(acc[i]), p3y = -f2hi(acc[i]);
        *(float2*)(P3 + r * SH + c0) = make_float2(p3x, p3y);
        float2 mv  = *(const float2*)(M  + r * SH + c0);
        float2 p2v = *(const float2*)(P2 + r * SH + c0);
        float d0 = (r == c0)     ? 1.f : 0.f;
        float d1 = (r == c0 + 1) ? 1.f : 0.f;
        float2 wv;
        wv.x = 1.38888889e-3f * d0 + 1.98412698e-4f * mv.x
             + 2.48015873e-5f * p2v.x + 2.75573192e-6f * p3x;
        wv.y = 1.38888889e-3f * d1 + 1.98412698e-4f * mv.y
             + 2.48015873e-5f * p2v.y + 2.75573192e-6f * p3y;
        *(float2*)(W + r * SH + c0) = wv;
    }
    __syncthreads();

    // T1 = B1 + P3*W = B1 - (P3t*W);  B1 = I/6 + M/24 + P2/120
    mm_acc(P3, W, acc, r0, c0);
    __syncthreads();                         // all reads of W done before overwrite
#pragma unroll
    for (int i = 0; i < 4; i++) {
        int r = r0 + i;
        float2 mv  = *(const float2*)(M  + r * SH + c0);
        float2 p2v = *(const float2*)(P2 + r * SH + c0);
        float d0 = (r == c0)     ? 1.f : 0.f;
        float d1 = (r == c0 + 1) ? 1.f : 0.f;
        float2 wv;
        wv.x = (1.f / 6.f) * d0 + (1.f / 24.f) * mv.x
             + (1.f / 120.f) * p2v.x - f2lo(acc[i]);
        wv.y = (1.f / 6.f) * d1 + (1.f / 24.f) * mv.y
             + (1.f / 120.f) * p2v.y - f2hi(acc[i]);
        *(float2*)(W + r * SH + c0) = wv;
    }
    __syncthreads();

    // E = B0 + P3*T1 = B0 - (P3t*T1);  B0 = I + M + P2/2
    mm_acc(P3, W, acc, r0, c0);
    float* dst = (h < 0) ? g_sos : g_powers[h][kk];
#pragma unroll
    for (int i = 0; i < 4; i++) {
        int r = r0 + i;
        float2 mv  = *(const float2*)(M  + r * SH + c0);
        float2 p2v = *(const float2*)(P2 + r * SH + c0);
        float d0 = (r == c0)     ? 1.f : 0.f;
        float d1 = (r == c0 + 1) ? 1.f : 0.f;
        float ex = d0 + mv.x + 0.5f * p2v.x - f2lo(acc[i]);
        float ey = d1 + mv.y + 0.5f * p2v.y - f2hi(acc[i]);
        *(float2*)(dst + r * 64 + c0) = make_float2(ex, ey);
        if (h >= 0 && kk == 1)    // publish identity as power 0 once per head
            *(float2*)(g_powers[h][0] + r * 64 + c0) = make_float2(d0, d1);
    }
}

// =================== kernel B: maps gather-broadcast (256 MB) ==============
__global__ void __launch_bounds__(256)
maps_writer(float4* __restrict__ out) {
    int b = blockIdx.x;
    int h = b & 7;
    int base = (b >> 3) << 3;
    int t = threadIdx.x;
    float4 v0, v1, v2, v3;
    int cached = -12345;
#pragma unroll 1
    for (int e = 0; e < 8; e++) {
        int n = g_perm[base + e];
        int key = g_key[n];
        if (key != cached) {
            const float4* src = (key == 100) ? (const float4*)g_sos
                                             : (const float4*)g_powers[h][key];
            v0 = src[t]; v1 = src[t + 256]; v2 = src[t + 512]; v3 = src[t + 768];
            cached = key;
        }
        float4* dst = out + ((size_t)((unsigned)(n * NHEADS + h)) << 10);
        __stcs(dst + t,       v0);
        __stcs(dst + t + 256, v1);
        __stcs(dst + t + 512, v2);
        __stcs(dst + t + 768, v3);
    }
}

// ---------------- launch --------------------------------------------------
extern "C" void kernel_launch(void* const* d_in, const int* in_sizes, int n_in,
                              void* d_out, int out_size) {
    const float* raw = (const float*)d_in[0];
    const int*   pw  = (const int*)d_in[1];
    const int L = in_sizes[1] / NMAX;
    float* out = (float*)d_out;

    size_t maps_elems = (size_t)NMAX * NHEADS * 4096;
    int has_steps = ((size_t)out_size >= maps_elems + (size_t)NMAX * NMAX) ? 1 : 0;

    size_t smem = 4ull * SZ * sizeof(float);   // 69632 B
    cudaFuncSetAttribute(kernelA, cudaFuncAttributeMaxDynamicSharedMemorySize,
                         (int)smem);

    kernelA<<<338, 512, smem>>>(raw, pw, L, out + maps_elems, has_steps);
    maps_writer<<<2048, 256>>>((float4*)out);
}